// round 14
// baseline (speedup 1.0000x reference)
#include <cuda_runtime.h>
#include <cuda_fp16.h>
#include <cuda_bf16.h>

#define NN 50000
#define EE 800000

// ---------------- scratch (no allocations allowed) ----------------
__device__ __half2 g_feat_h[NN * 64];   // ATTN fc output, fp16 [N, 128]
__device__ __half2 g_agg_h [NN * 64];   // conv output (agg+bias), fp16 [N, 128]
__device__ __half2 g_x_h   [NN * 32];   // layer-1 lin+relu output, fp16 [N, 64]
__device__ float g_el  [NN * 2];
__device__ float g_er  [NN * 2];
// CSR scratch (g_cnt is zero at load; k_scan23 re-zeros it after use)
__device__ int g_cnt[NN];
__device__ int g_tmp[NN];
__device__ int g_rowptr[NN + 1];
__device__ int g_rank[EE];           // within-bucket rank per edge (from k_hist)
__device__ int g_srcs[EE];
__device__ int g_bsum[128];

// ---------------- helpers ----------------
__device__ __forceinline__ unsigned f2tf(float x) {
    unsigned u;
    asm("cvt.rna.tf32.f32 %0, %1;" : "=r"(u) : "f"(x));
    return u;
}
__device__ __forceinline__ void pdl_wait() {
    cudaGridDependencySynchronize();
}

// ======================= tf32 tensor-core GEMM (+ fused attn logits) ==========
// C[n,M] = A[n,K] @ W[K,M] (+bias,+relu). 128x64 tile, 256 thr, m16n8k8 mma.
// AHALF: A is fp16 (__half row-major). CHALF: C written as fp16.
// ATTN: M==128, blockIdx.y == head; epilogue writes fp16 feat + g_el/g_er.
// TRIG: fire programmatic-launch trigger early (next kernel is independent).
template<int K, int M, bool ATTN, bool TRIG, bool AHALF, bool CHALF>
__global__ void __launch_bounds__(256)
gemm_mma(const void* __restrict__ Av, const float* __restrict__ W,
         const float* __restrict__ bias, void* __restrict__ Cv,
         int n, int relu, const float* __restrict__ al, const float* __restrict__ ar) {
    pdl_wait();
    if (TRIG) cudaTriggerProgrammaticLaunchCompletion();
    __shared__ float As[128][36];
    __shared__ float Ws[32][72];
    const float* Af = (const float*)Av;
    const __half* Ah = (const __half*)Av;
    int tid  = threadIdx.x;
    int lane = tid & 31, warp = tid >> 5;
    int g = lane >> 2, t4 = lane & 3;
    int r0 = blockIdx.x * 128;
    int c0 = blockIdx.y * 64;

    float acc[8][4];
    #pragma unroll
    for (int i = 0; i < 8; i++)
        #pragma unroll
        for (int j = 0; j < 4; j++) acc[i][j] = 0.f;

    float4 va[4]; uint2 vah[4]; float4 vw[2];

    #pragma unroll
    for (int it = 0; it < 4; it++) {
        int f4 = tid + it * 256;
        int row = f4 >> 3, kq = (f4 & 7) * 4;
        if (AHALF) {
            vah[it] = make_uint2(0u, 0u);
            if (r0 + row < n) vah[it] = *(const uint2*)&Ah[(size_t)(r0 + row) * K + kq];
        } else {
            va[it] = make_float4(0.f, 0.f, 0.f, 0.f);
            if (r0 + row < n) va[it] = *(const float4*)&Af[(size_t)(r0 + row) * K + kq];
        }
    }
    #pragma unroll
    for (int it = 0; it < 2; it++) {
        int f4 = tid + it * 256;
        int k = f4 >> 4, cq = (f4 & 15) * 4;
        vw[it] = *(const float4*)&W[(size_t)k * M + c0 + cq];
    }

    for (int kc = 0; kc < K; kc += 32) {
        #pragma unroll
        for (int it = 0; it < 4; it++) {
            int f4 = tid + it * 256;
            int row = f4 >> 3, kq = (f4 & 7) * 4;
            if (AHALF) {
                float2 p0 = __half22float2(*(const __half2*)&vah[it].x);
                float2 p1 = __half22float2(*(const __half2*)&vah[it].y);
                As[row][kq + 0] = p0.x;
                As[row][kq + 1] = p0.y;
                As[row][kq + 2] = p1.x;
                As[row][kq + 3] = p1.y;
            } else {
                As[row][kq + 0] = __uint_as_float(f2tf(va[it].x));
                As[row][kq + 1] = __uint_as_float(f2tf(va[it].y));
                As[row][kq + 2] = __uint_as_float(f2tf(va[it].z));
                As[row][kq + 3] = __uint_as_float(f2tf(va[it].w));
            }
        }
        #pragma unroll
        for (int it = 0; it < 2; it++) {
            int f4 = tid + it * 256;
            int k = f4 >> 4, cq = (f4 & 15) * 4;
            Ws[k][cq + 0] = __uint_as_float(f2tf(vw[it].x));
            Ws[k][cq + 1] = __uint_as_float(f2tf(vw[it].y));
            Ws[k][cq + 2] = __uint_as_float(f2tf(vw[it].z));
            Ws[k][cq + 3] = __uint_as_float(f2tf(vw[it].w));
        }
        __syncthreads();

        if (kc + 32 < K) {
            #pragma unroll
            for (int it = 0; it < 4; it++) {
                int f4 = tid + it * 256;
                int row = f4 >> 3, kq = (f4 & 7) * 4;
                if (AHALF) {
                    vah[it] = make_uint2(0u, 0u);
                    if (r0 + row < n)
                        vah[it] = *(const uint2*)&Ah[(size_t)(r0 + row) * K + kc + 32 + kq];
                } else {
                    va[it] = make_float4(0.f, 0.f, 0.f, 0.f);
                    if (r0 + row < n)
                        va[it] = *(const float4*)&Af[(size_t)(r0 + row) * K + kc + 32 + kq];
                }
            }
            #pragma unroll
            for (int it = 0; it < 2; it++) {
                int f4 = tid + it * 256;
                int k = f4 >> 4, cq = (f4 & 15) * 4;
                vw[it] = *(const float4*)&W[(size_t)(kc + 32 + k) * M + c0 + cq];
            }
        }

        int wr = warp * 16;
        #pragma unroll
        for (int kk = 0; kk < 4; kk++) {
            unsigned a0 = __float_as_uint(As[wr + g    ][kk * 8 + t4    ]);
            unsigned a1 = __float_as_uint(As[wr + g + 8][kk * 8 + t4    ]);
            unsigned a2 = __float_as_uint(As[wr + g    ][kk * 8 + t4 + 4]);
            unsigned a3 = __float_as_uint(As[wr + g + 8][kk * 8 + t4 + 4]);
            #pragma unroll
            for (int nt = 0; nt < 8; nt++) {
                unsigned b0 = __float_as_uint(Ws[kk * 8 + t4    ][nt * 8 + g]);
                unsigned b1 = __float_as_uint(Ws[kk * 8 + t4 + 4][nt * 8 + g]);
                asm volatile(
                    "mma.sync.aligned.m16n8k8.row.col.f32.tf32.tf32.f32 "
                    "{%0,%1,%2,%3}, {%4,%5,%6,%7}, {%8,%9}, {%0,%1,%2,%3};"
                    : "+f"(acc[nt][0]), "+f"(acc[nt][1]),
                      "+f"(acc[nt][2]), "+f"(acc[nt][3])
                    : "r"(a0), "r"(a1), "r"(a2), "r"(a3), "r"(b0), "r"(b1));
            }
        }
        __syncthreads();
    }

    int wr = warp * 16;
    float el0 = 0.f, er0 = 0.f, el1 = 0.f, er1 = 0.f;
    int head = blockIdx.y;
    #pragma unroll
    for (int nt = 0; nt < 8; nt++) {
        int col = c0 + nt * 8 + t4 * 2;
        float bx = 0.f, by = 0.f;
        if (bias) { bx = bias[col]; by = bias[col + 1]; }
        float v0 = acc[nt][0] + bx, v1 = acc[nt][1] + by;
        float v2 = acc[nt][2] + bx, v3 = acc[nt][3] + by;
        if (relu) {
            v0 = fmaxf(v0, 0.f); v1 = fmaxf(v1, 0.f);
            v2 = fmaxf(v2, 0.f); v3 = fmaxf(v3, 0.f);
        }
        int row0 = r0 + wr + g, row1 = row0 + 8;
        if (ATTN) {
            int lc = head * 64 + nt * 8 + t4 * 2;
            float a0 = al[lc], a1 = al[lc + 1];
            float q0 = ar[lc], q1 = ar[lc + 1];
            el0 = fmaf(v0, a0, fmaf(v1, a1, el0));
            er0 = fmaf(v0, q0, fmaf(v1, q1, er0));
            el1 = fmaf(v2, a0, fmaf(v3, a1, el1));
            er1 = fmaf(v2, q0, fmaf(v3, q1, er1));
            int hc = head * 32 + nt * 4 + t4;
            if (row0 < n) g_feat_h[(size_t)row0 * 64 + hc] = __floats2half2_rn(v0, v1);
            if (row1 < n) g_feat_h[(size_t)row1 * 64 + hc] = __floats2half2_rn(v2, v3);
        } else if (CHALF) {
            __half2* Ch = (__half2*)Cv;
            if (row0 < n) Ch[((size_t)row0 * M + col) >> 1] = __floats2half2_rn(v0, v1);
            if (row1 < n) Ch[((size_t)row1 * M + col) >> 1] = __floats2half2_rn(v2, v3);
        } else {
            float* Cf = (float*)Cv;
            if (row0 < n) *(float2*)&Cf[(size_t)row0 * M + col] = make_float2(v0, v1);
            if (row1 < n) *(float2*)&Cf[(size_t)row1 * M + col] = make_float2(v2, v3);
        }
    }
    if (ATTN) {
        #pragma unroll
        for (int o = 1; o <= 2; o <<= 1) {
            el0 += __shfl_xor_sync(0xffffffffu, el0, o);
            er0 += __shfl_xor_sync(0xffffffffu, er0, o);
            el1 += __shfl_xor_sync(0xffffffffu, el1, o);
            er1 += __shfl_xor_sync(0xffffffffu, er1, o);
        }
        if (t4 == 0) {
            int row0 = r0 + wr + g, row1 = row0 + 8;
            if (row0 < n) { g_el[row0 * 2 + head] = el0; g_er[row0 * 2 + head] = er0; }
            if (row1 < n) { g_el[row1 * 2 + head] = el1; g_er[row1 * 2 + head] = er1; }
        }
    }
}

// ======================= CSR build =======================
// hist runs CONCURRENTLY with the layer-1 ATTN GEMM (no grid sync: it reads
// only the dst input and g_cnt, which the previous call's k_scan23 re-zeroed).
__global__ void k_hist(const int* __restrict__ dst) {
    int e = blockIdx.x * blockDim.x + threadIdx.x;
    if (e < EE) {
        int p = atomicAdd(&g_cnt[dst[e]], 1);
        g_rank[e] = p;
    }
}
__global__ void k_scan1() {   // 98 blocks x 512: per-block inclusive scans
    pdl_wait();
    __shared__ int s[512];
    int i = blockIdx.x * 512 + threadIdx.x;
    int v = (i < NN) ? g_cnt[i] : 0;
    s[threadIdx.x] = v;
    __syncthreads();
    for (int off = 1; off < 512; off <<= 1) {
        int t = (threadIdx.x >= off) ? s[threadIdx.x - off] : 0;
        __syncthreads();
        s[threadIdx.x] += t;
        __syncthreads();
    }
    if (i < NN) g_tmp[i] = s[threadIdx.x];
    if (threadIdx.x == 511) g_bsum[blockIdx.x] = s[511];
}
// scan2+scan3 merged: every block redundantly scans the 98 block sums (cheap),
// then finalizes rowptr and restores g_cnt = 0.
__global__ void k_scan23() {
    pdl_wait();
    __shared__ int sb[128];
    int tid = threadIdx.x;
    if (tid < 128) sb[tid] = (tid < 98) ? g_bsum[tid] : 0;
    __syncthreads();
    for (int off = 1; off < 128; off <<= 1) {
        int t = (tid < 128 && tid >= off) ? sb[tid - off] : 0;
        __syncthreads();
        if (tid < 128) sb[tid] += t;
        __syncthreads();
    }
    int i = blockIdx.x * blockDim.x + tid;
    if (i >= NN) return;
    int j = i >> 9;
    int off = (j == 0) ? 0 : sb[j - 1];
    int excl = g_tmp[i] - g_cnt[i] + off;
    g_rowptr[i] = excl;
    g_cnt[i]    = 0;
    if (i == NN - 1) g_rowptr[NN] = g_tmp[i] + off;
}
// atomic-free scatter: position = rowptr[dst] + rank (recorded by k_hist)
__global__ void k_scatter(const int* __restrict__ src, const int* __restrict__ dst) {
    pdl_wait();
    int e = blockIdx.x * blockDim.x + threadIdx.x;
    if (e >= EE) return;
    int d = dst[e];
    g_srcs[g_rowptr[d] + g_rank[e]] = src[e];
}

// ======================= fused edge-softmax + aggregation =======================
// one warp per dst node; fp16 feat gather (256 B/row = 32 uint2), fp32 accumulate,
// fp16 output (g_agg_h). 512-thread blocks (16 warps) to halve block count.
__global__ void __launch_bounds__(512)
gat_agg(const float* __restrict__ bias) {
    pdl_wait();
    __shared__ float2 s_ex[16][32];
    __shared__ int    s_src[16][32];
    int lane = threadIdx.x & 31, w = threadIdx.x >> 5;
    int d = blockIdx.x * 16 + w;
    if (d >= NN) return;
    int beg = g_rowptr[d], end = g_rowptr[d + 1];
    float2 er2 = *(const float2*)(g_er + 2 * d);
    const uint2* feath = (const uint2*)g_feat_h;

    float4 acc = make_float4(0.f, 0.f, 0.f, 0.f);
    float z0 = 0.f, z1 = 0.f;

    for (int c = beg; c < end; c += 32) {
        int idx = c + lane;
        bool valid = idx < end;
        int s = valid ? g_srcs[idx] : 0;
        float2 el2 = *(const float2*)(g_el + 2 * s);
        float e0 = el2.x + er2.x; e0 = e0 > 0.f ? e0 : 0.2f * e0;
        float e1 = el2.y + er2.y; e1 = e1 > 0.f ? e1 : 0.2f * e1;
        float x0 = valid ? __expf(e0) : 0.f;
        float x1 = valid ? __expf(e1) : 0.f;
        z0 += x0; z1 += x1;
        s_ex[w][lane]  = make_float2(x0, x1);
        s_src[w][lane] = s;
        __syncwarp();
        int m = min(32, end - c);
        #pragma unroll 4
        for (int j = 0; j < m; j++) {
            int sj = s_src[w][j];
            float2 exj = s_ex[w][j];
            float wgt = (lane < 16) ? exj.x : exj.y;
            uint2 u = feath[(size_t)sj * 32 + lane];
            float2 fa = __half22float2(*(const __half2*)&u.x);
            float2 fb = __half22float2(*(const __half2*)&u.y);
            acc.x = fmaf(wgt, fa.x, acc.x);
            acc.y = fmaf(wgt, fa.y, acc.y);
            acc.z = fmaf(wgt, fb.x, acc.z);
            acc.w = fmaf(wgt, fb.y, acc.w);
        }
        __syncwarp();
    }
    #pragma unroll
    for (int o = 16; o > 0; o >>= 1) {
        z0 += __shfl_xor_sync(0xffffffffu, z0, o);
        z1 += __shfl_xor_sync(0xffffffffu, z1, o);
    }
    float z = (lane < 16) ? z0 : z1;
    float ia = (z > 0.f) ? __fdividef(1.f, z) : 0.f;
    float4 b4 = ((const float4*)bias)[lane];
    float4 o4;
    o4.x = fmaf(acc.x, ia, b4.x);
    o4.y = fmaf(acc.y, ia, b4.y);
    o4.z = fmaf(acc.z, ia, b4.z);
    o4.w = fmaf(acc.w, ia, b4.w);
    uint2 outw;
    *(__half2*)&outw.x = __floats2half2_rn(o4.x, o4.y);
    *(__half2*)&outw.y = __floats2half2_rn(o4.z, o4.w);
    ((uint2*)g_agg_h)[(size_t)d * 32 + lane] = outw;
}

// ======================= host =======================
template<typename... Args>
static inline void pdl_launch(dim3 gd, dim3 bd, void (*kfn)(Args...), Args... args) {
    cudaLaunchConfig_t cfg = {};
    cfg.gridDim = gd;
    cfg.blockDim = bd;
    cudaLaunchAttribute at[1];
    at[0].id = cudaLaunchAttributeProgrammaticStreamSerialization;
    at[0].val.programmaticStreamSerializationAllowed = 1;
    cfg.attrs = at;
    cfg.numAttrs = 1;
    cudaLaunchKernelEx(&cfg, kfn, args...);
}

extern "C" void kernel_launch(void* const* d_in, const int* in_sizes, int n_in,
                              void* d_out, int out_size) {
    const float* h     = (const float*)d_in[0];
    const int*   src   = (const int*)d_in[1];
    const int*   dst   = (const int*)d_in[2];
    const float* W1    = (const float*)d_in[3];
    const float* al1   = (const float*)d_in[4];
    const float* ar1   = (const float*)d_in[5];
    const float* b1    = (const float*)d_in[6];
    const float* lin1W = (const float*)d_in[7];
    const float* lin1b = (const float*)d_in[8];
    const float* W2    = (const float*)d_in[9];
    const float* al2   = (const float*)d_in[10];
    const float* ar2   = (const float*)d_in[11];
    const float* b2    = (const float*)d_in[12];
    const float* lin2W = (const float*)d_in[13];
    const float* lin2b = (const float*)d_in[14];
    float* out = (float*)d_out;

    void *aggp, *xp;
    cudaGetSymbolAddress(&aggp, g_agg_h);
    cudaGetSymbolAddress(&xp,   g_x_h);

    const int ROWT  = (NN + 127) / 128;           // 391
    const int NB    = (NN + 255) / 256;           // 196
    const int EB    = (EE + 255) / 256;           // 3125
    const int AGGB  = (NN + 15) / 16;             // 3125 (16 warps/block)

    const float* nfc = nullptr;
    void*        nv  = nullptr;

    // ---- layer-1 feat GEMM first (TRIG=true: fires early so k_hist overlaps) ----
    pdl_launch(dim3(ROWT, 2), dim3(256), gemm_mma<128, 128, true, true, false, false>,
               (const void*)h, W1, nfc, nv, (int)NN, 0, al1, ar1);

    // ---- CSR build (hist overlaps gemm1; rest is a dependent chain) ----
    pdl_launch(dim3(EB), dim3(256), k_hist, dst);
    pdl_launch(dim3(98), dim3(512), k_scan1);
    pdl_launch(dim3(NB), dim3(256), k_scan23);
    pdl_launch(dim3(EB), dim3(256), k_scatter, src, dst);

    // ---- layer 1 aggregation + lin ----
    pdl_launch(dim3(AGGB), dim3(512), gat_agg, b1);
    pdl_launch(dim3(ROWT, 1), dim3(256), gemm_mma<128, 64, false, false, true, true>,
               (const void*)aggp, lin1W, lin1b, xp, (int)NN, 1, nfc, nfc);

    // ---- layer 2 ----
    pdl_launch(dim3(ROWT, 2), dim3(256), gemm_mma<64, 128, true, false, true, false>,
               (const void*)xp, W2, nfc, nv, (int)NN, 0, al2, ar2);
    pdl_launch(dim3(AGGB), dim3(512), gat_agg, b2);
    pdl_launch(dim3(ROWT, 1), dim3(256), gemm_mma<128, 64, false, false, true, false>,
               (const void*)aggp, lin2W, lin2b, (void*)out, (int)NN, 0, nfc, nfc);
}

// round 15
// speedup vs baseline: 1.0295x; 1.0295x over previous
#include <cuda_runtime.h>
#include <cuda_fp16.h>
#include <cuda_bf16.h>

#define NN 50000
#define EE 800000

// ---------------- scratch (no allocations allowed) ----------------
__device__ __half2 g_feat_h[NN * 64];   // ATTN fc output, fp16 [N, 128]
__device__ __half2 g_agg_h [NN * 64];   // conv output (agg+bias), fp16 [N, 128]
__device__ __half2 g_x_h   [NN * 32];   // layer-1 lin+relu output, fp16 [N, 64]
__device__ float g_el  [NN * 2];
__device__ float g_er  [NN * 2];
// CSR scratch (g_cnt is zero at load; k_scan23 re-zeros it after use)
__device__ int g_cnt[NN];
__device__ int g_tmp[NN];
__device__ int g_rowptr[NN + 1];
__device__ int g_rank[EE];           // within-bucket rank per edge (from k_hist)
__device__ int g_srcs[EE];
__device__ int g_bsum[128];

// ---------------- helpers ----------------
__device__ __forceinline__ unsigned f2tf(float x) {
    unsigned u;
    asm("cvt.rna.tf32.f32 %0, %1;" : "=r"(u) : "f"(x));
    return u;
}
__device__ __forceinline__ void pdl_wait() {
    cudaGridDependencySynchronize();
}
// warp-inclusive scan (32 lanes)
__device__ __forceinline__ int warp_iscan(int x, int lane) {
    #pragma unroll
    for (int off = 1; off < 32; off <<= 1) {
        int t = __shfl_up_sync(0xffffffffu, x, off);
        if (lane >= off) x += t;
    }
    return x;
}

// ======================= tf32 tensor-core GEMM (+ fused attn logits) ==========
// C[n,M] = A[n,K] @ W[K,M] (+bias,+relu). 128x64 tile, 256 thr, m16n8k8 mma.
// AHALF: A is fp16 (__half row-major). CHALF: C written as fp16.
// ATTN: M==128, blockIdx.y == head; epilogue writes fp16 feat + g_el/g_er.
// TRIG: fire programmatic-launch trigger early (next kernel is independent).
template<int K, int M, bool ATTN, bool TRIG, bool AHALF, bool CHALF>
__global__ void __launch_bounds__(256)
gemm_mma(const void* __restrict__ Av, const float* __restrict__ W,
         const float* __restrict__ bias, void* __restrict__ Cv,
         int n, int relu, const float* __restrict__ al, const float* __restrict__ ar) {
    pdl_wait();
    if (TRIG) cudaTriggerProgrammaticLaunchCompletion();
    __shared__ float As[128][36];
    __shared__ float Ws[32][72];
    const float* Af = (const float*)Av;
    const __half* Ah = (const __half*)Av;
    int tid  = threadIdx.x;
    int lane = tid & 31, warp = tid >> 5;
    int g = lane >> 2, t4 = lane & 3;
    int r0 = blockIdx.x * 128;
    int c0 = blockIdx.y * 64;

    float acc[8][4];
    #pragma unroll
    for (int i = 0; i < 8; i++)
        #pragma unroll
        for (int j = 0; j < 4; j++) acc[i][j] = 0.f;

    float4 va[4]; uint2 vah[4]; float4 vw[2];

    #pragma unroll
    for (int it = 0; it < 4; it++) {
        int f4 = tid + it * 256;
        int row = f4 >> 3, kq = (f4 & 7) * 4;
        if (AHALF) {
            vah[it] = make_uint2(0u, 0u);
            if (r0 + row < n) vah[it] = *(const uint2*)&Ah[(size_t)(r0 + row) * K + kq];
        } else {
            va[it] = make_float4(0.f, 0.f, 0.f, 0.f);
            if (r0 + row < n) va[it] = *(const float4*)&Af[(size_t)(r0 + row) * K + kq];
        }
    }
    #pragma unroll
    for (int it = 0; it < 2; it++) {
        int f4 = tid + it * 256;
        int k = f4 >> 4, cq = (f4 & 15) * 4;
        vw[it] = *(const float4*)&W[(size_t)k * M + c0 + cq];
    }

    for (int kc = 0; kc < K; kc += 32) {
        #pragma unroll
        for (int it = 0; it < 4; it++) {
            int f4 = tid + it * 256;
            int row = f4 >> 3, kq = (f4 & 7) * 4;
            if (AHALF) {
                float2 p0 = __half22float2(*(const __half2*)&vah[it].x);
                float2 p1 = __half22float2(*(const __half2*)&vah[it].y);
                As[row][kq + 0] = p0.x;
                As[row][kq + 1] = p0.y;
                As[row][kq + 2] = p1.x;
                As[row][kq + 3] = p1.y;
            } else {
                As[row][kq + 0] = __uint_as_float(f2tf(va[it].x));
                As[row][kq + 1] = __uint_as_float(f2tf(va[it].y));
                As[row][kq + 2] = __uint_as_float(f2tf(va[it].z));
                As[row][kq + 3] = __uint_as_float(f2tf(va[it].w));
            }
        }
        #pragma unroll
        for (int it = 0; it < 2; it++) {
            int f4 = tid + it * 256;
            int k = f4 >> 4, cq = (f4 & 15) * 4;
            Ws[k][cq + 0] = __uint_as_float(f2tf(vw[it].x));
            Ws[k][cq + 1] = __uint_as_float(f2tf(vw[it].y));
            Ws[k][cq + 2] = __uint_as_float(f2tf(vw[it].z));
            Ws[k][cq + 3] = __uint_as_float(f2tf(vw[it].w));
        }
        __syncthreads();

        if (kc + 32 < K) {
            #pragma unroll
            for (int it = 0; it < 4; it++) {
                int f4 = tid + it * 256;
                int row = f4 >> 3, kq = (f4 & 7) * 4;
                if (AHALF) {
                    vah[it] = make_uint2(0u, 0u);
                    if (r0 + row < n)
                        vah[it] = *(const uint2*)&Ah[(size_t)(r0 + row) * K + kc + 32 + kq];
                } else {
                    va[it] = make_float4(0.f, 0.f, 0.f, 0.f);
                    if (r0 + row < n)
                        va[it] = *(const float4*)&Af[(size_t)(r0 + row) * K + kc + 32 + kq];
                }
            }
            #pragma unroll
            for (int it = 0; it < 2; it++) {
                int f4 = tid + it * 256;
                int k = f4 >> 4, cq = (f4 & 15) * 4;
                vw[it] = *(const float4*)&W[(size_t)(kc + 32 + k) * M + c0 + cq];
            }
        }

        int wr = warp * 16;
        #pragma unroll
        for (int kk = 0; kk < 4; kk++) {
            unsigned a0 = __float_as_uint(As[wr + g    ][kk * 8 + t4    ]);
            unsigned a1 = __float_as_uint(As[wr + g + 8][kk * 8 + t4    ]);
            unsigned a2 = __float_as_uint(As[wr + g    ][kk * 8 + t4 + 4]);
            unsigned a3 = __float_as_uint(As[wr + g + 8][kk * 8 + t4 + 4]);
            #pragma unroll
            for (int nt = 0; nt < 8; nt++) {
                unsigned b0 = __float_as_uint(Ws[kk * 8 + t4    ][nt * 8 + g]);
                unsigned b1 = __float_as_uint(Ws[kk * 8 + t4 + 4][nt * 8 + g]);
                asm volatile(
                    "mma.sync.aligned.m16n8k8.row.col.f32.tf32.tf32.f32 "
                    "{%0,%1,%2,%3}, {%4,%5,%6,%7}, {%8,%9}, {%0,%1,%2,%3};"
                    : "+f"(acc[nt][0]), "+f"(acc[nt][1]),
                      "+f"(acc[nt][2]), "+f"(acc[nt][3])
                    : "r"(a0), "r"(a1), "r"(a2), "r"(a3), "r"(b0), "r"(b1));
            }
        }
        __syncthreads();
    }

    int wr = warp * 16;
    float el0 = 0.f, er0 = 0.f, el1 = 0.f, er1 = 0.f;
    int head = blockIdx.y;
    #pragma unroll
    for (int nt = 0; nt < 8; nt++) {
        int col = c0 + nt * 8 + t4 * 2;
        float bx = 0.f, by = 0.f;
        if (bias) { bx = bias[col]; by = bias[col + 1]; }
        float v0 = acc[nt][0] + bx, v1 = acc[nt][1] + by;
        float v2 = acc[nt][2] + bx, v3 = acc[nt][3] + by;
        if (relu) {
            v0 = fmaxf(v0, 0.f); v1 = fmaxf(v1, 0.f);
            v2 = fmaxf(v2, 0.f); v3 = fmaxf(v3, 0.f);
        }
        int row0 = r0 + wr + g, row1 = row0 + 8;
        if (ATTN) {
            int lc = head * 64 + nt * 8 + t4 * 2;
            float a0 = al[lc], a1 = al[lc + 1];
            float q0 = ar[lc], q1 = ar[lc + 1];
            el0 = fmaf(v0, a0, fmaf(v1, a1, el0));
            er0 = fmaf(v0, q0, fmaf(v1, q1, er0));
            el1 = fmaf(v2, a0, fmaf(v3, a1, el1));
            er1 = fmaf(v2, q0, fmaf(v3, q1, er1));
            int hc = head * 32 + nt * 4 + t4;
            if (row0 < n) g_feat_h[(size_t)row0 * 64 + hc] = __floats2half2_rn(v0, v1);
            if (row1 < n) g_feat_h[(size_t)row1 * 64 + hc] = __floats2half2_rn(v2, v3);
        } else if (CHALF) {
            __half2* Ch = (__half2*)Cv;
            if (row0 < n) Ch[((size_t)row0 * M + col) >> 1] = __floats2half2_rn(v0, v1);
            if (row1 < n) Ch[((size_t)row1 * M + col) >> 1] = __floats2half2_rn(v2, v3);
        } else {
            float* Cf = (float*)Cv;
            if (row0 < n) *(float2*)&Cf[(size_t)row0 * M + col] = make_float2(v0, v1);
            if (row1 < n) *(float2*)&Cf[(size_t)row1 * M + col] = make_float2(v2, v3);
        }
    }
    if (ATTN) {
        #pragma unroll
        for (int o = 1; o <= 2; o <<= 1) {
            el0 += __shfl_xor_sync(0xffffffffu, el0, o);
            er0 += __shfl_xor_sync(0xffffffffu, er0, o);
            el1 += __shfl_xor_sync(0xffffffffu, el1, o);
            er1 += __shfl_xor_sync(0xffffffffu, er1, o);
        }
        if (t4 == 0) {
            int row0 = r0 + wr + g, row1 = row0 + 8;
            if (row0 < n) { g_el[row0 * 2 + head] = el0; g_er[row0 * 2 + head] = er0; }
            if (row1 < n) { g_el[row1 * 2 + head] = el1; g_er[row1 * 2 + head] = er1; }
        }
    }
}

// ======================= CSR build =======================
// hist runs CONCURRENTLY with the layer-1 ATTN GEMM (no grid sync: it reads
// only the dst input and g_cnt, which the previous call's k_scan23 re-zeroed).
__global__ void __launch_bounds__(512) k_hist(const int* __restrict__ dst) {
    int e = blockIdx.x * blockDim.x + threadIdx.x;
    if (e < EE) {
        int p = atomicAdd(&g_cnt[dst[e]], 1);
        g_rank[e] = p;
    }
}
// 98 blocks x 512: per-block inclusive scans, warp-shuffle based (2 barriers)
__global__ void __launch_bounds__(512) k_scan1() {
    pdl_wait();
    __shared__ int wsum[16];
    int tid = threadIdx.x, lane = tid & 31, wid = tid >> 5;
    int i = blockIdx.x * 512 + tid;
    int v = (i < NN) ? g_cnt[i] : 0;
    int x = warp_iscan(v, lane);                 // inclusive within warp
    if (lane == 31) wsum[wid] = x;
    __syncthreads();
    if (wid == 0) {
        int s = (lane < 16) ? wsum[lane] : 0;
        s = warp_iscan(s, lane);
        if (lane < 16) wsum[lane] = s;           // inclusive scan of warp totals
    }
    __syncthreads();
    int base = (wid > 0) ? wsum[wid - 1] : 0;
    int incl = base + x;
    if (i < NN) g_tmp[i] = incl;
    if (tid == 511) g_bsum[blockIdx.x] = incl;   // block total
}
// scan2+scan3 merged, warp-shuffle based: every block redundantly scans the 98
// block sums, then finalizes rowptr and restores g_cnt = 0. (2 barriers)
__global__ void __launch_bounds__(256) k_scan23() {
    pdl_wait();
    __shared__ int sb[128];
    __shared__ int wtot[4];
    int tid = threadIdx.x, lane = tid & 31, wid = tid >> 5;
    // warps 0-3 scan the 128 block sums (32 each)
    if (wid < 4) {
        int t = wid * 32 + lane;
        int v = (t < 98) ? g_bsum[t] : 0;
        int x = warp_iscan(v, lane);
        sb[t] = x;
        if (lane == 31) wtot[wid] = x;
    }
    __syncthreads();
    int i = blockIdx.x * blockDim.x + tid;
    if (i >= NN) return;
    int j = i >> 9;                              // which 512-block
    // inclusive prefix over block sums up to j-1:
    int off = 0;
    if (j > 0) {
        int jw = (j - 1) >> 5;                   // warp that holds sb[j-1]
        off = sb[j - 1];
        #pragma unroll
        for (int k = 0; k < 4; k++)
            if (k < jw) off += wtot[k];
    }
    int excl = g_tmp[i] - g_cnt[i] + off;
    g_rowptr[i] = excl;
    g_cnt[i]    = 0;                 // restore invariant: g_cnt==0 at next call
    if (i == NN - 1) g_rowptr[NN] = g_tmp[i] + off;
}
// atomic-free scatter: position = rowptr[dst] + rank (recorded by k_hist)
__global__ void __launch_bounds__(512) k_scatter(const int* __restrict__ src,
                                                 const int* __restrict__ dst) {
    pdl_wait();
    int e = blockIdx.x * blockDim.x + threadIdx.x;
    if (e >= EE) return;
    int d = dst[e];
    g_srcs[g_rowptr[d] + g_rank[e]] = src[e];
}

// ======================= fused edge-softmax + aggregation =======================
// one warp per dst node; fp16 feat gather (256 B/row = 32 uint2), fp32 accumulate,
// fp16 output (g_agg_h). 256-thread/8-warp blocks (R11-proven config).
__global__ void __launch_bounds__(256)
gat_agg(const float* __restrict__ bias) {
    pdl_wait();
    __shared__ float2 s_ex[8][32];
    __shared__ int    s_src[8][32];
    int lane = threadIdx.x & 31, w = threadIdx.x >> 5;
    int d = blockIdx.x * 8 + w;
    if (d >= NN) return;
    int beg = g_rowptr[d], end = g_rowptr[d + 1];
    float2 er2 = *(const float2*)(g_er + 2 * d);
    const uint2* feath = (const uint2*)g_feat_h;

    float4 acc = make_float4(0.f, 0.f, 0.f, 0.f);
    float z0 = 0.f, z1 = 0.f;

    for (int c = beg; c < end; c += 32) {
        int idx = c + lane;
        bool valid = idx < end;
        int s = valid ? g_srcs[idx] : 0;
        float2 el2 = *(const float2*)(g_el + 2 * s);
        float e0 = el2.x + er2.x; e0 = e0 > 0.f ? e0 : 0.2f * e0;
        float e1 = el2.y + er2.y; e1 = e1 > 0.f ? e1 : 0.2f * e1;
        float x0 = valid ? __expf(e0) : 0.f;
        float x1 = valid ? __expf(e1) : 0.f;
        z0 += x0; z1 += x1;
        s_ex[w][lane]  = make_float2(x0, x1);
        s_src[w][lane] = s;
        __syncwarp();
        int m = min(32, end - c);
        #pragma unroll 4
        for (int j = 0; j < m; j++) {
            int sj = s_src[w][j];
            float2 exj = s_ex[w][j];
            float wgt = (lane < 16) ? exj.x : exj.y;
            uint2 u = feath[(size_t)sj * 32 + lane];
            float2 fa = __half22float2(*(const __half2*)&u.x);
            float2 fb = __half22float2(*(const __half2*)&u.y);
            acc.x = fmaf(wgt, fa.x, acc.x);
            acc.y = fmaf(wgt, fa.y, acc.y);
            acc.z = fmaf(wgt, fb.x, acc.z);
            acc.w = fmaf(wgt, fb.y, acc.w);
        }
        __syncwarp();
    }
    #pragma unroll
    for (int o = 16; o > 0; o >>= 1) {
        z0 += __shfl_xor_sync(0xffffffffu, z0, o);
        z1 += __shfl_xor_sync(0xffffffffu, z1, o);
    }
    float z = (lane < 16) ? z0 : z1;
    float ia = (z > 0.f) ? __fdividef(1.f, z) : 0.f;
    float4 b4 = ((const float4*)bias)[lane];
    float4 o4;
    o4.x = fmaf(acc.x, ia, b4.x);
    o4.y = fmaf(acc.y, ia, b4.y);
    o4.z = fmaf(acc.z, ia, b4.z);
    o4.w = fmaf(acc.w, ia, b4.w);
    uint2 outw;
    *(__half2*)&outw.x = __floats2half2_rn(o4.x, o4.y);
    *(__half2*)&outw.y = __floats2half2_rn(o4.z, o4.w);
    ((uint2*)g_agg_h)[(size_t)d * 32 + lane] = outw;
}

// ======================= host =======================
template<typename... Args>
static inline void pdl_launch(dim3 gd, dim3 bd, void (*kfn)(Args...), Args... args) {
    cudaLaunchConfig_t cfg = {};
    cfg.gridDim = gd;
    cfg.blockDim = bd;
    cudaLaunchAttribute at[1];
    at[0].id = cudaLaunchAttributeProgrammaticStreamSerialization;
    at[0].val.programmaticStreamSerializationAllowed = 1;
    cfg.attrs = at;
    cfg.numAttrs = 1;
    cudaLaunchKernelEx(&cfg, kfn, args...);
}

extern "C" void kernel_launch(void* const* d_in, const int* in_sizes, int n_in,
                              void* d_out, int out_size) {
    const float* h     = (const float*)d_in[0];
    const int*   src   = (const int*)d_in[1];
    const int*   dst   = (const int*)d_in[2];
    const float* W1    = (const float*)d_in[3];
    const float* al1   = (const float*)d_in[4];
    const float* ar1   = (const float*)d_in[5];
    const float* b1    = (const float*)d_in[6];
    const float* lin1W = (const float*)d_in[7];
    const float* lin1b = (const float*)d_in[8];
    const float* W2    = (const float*)d_in[9];
    const float* al2   = (const float*)d_in[10];
    const float* ar2   = (const float*)d_in[11];
    const float* b2    = (const float*)d_in[12];
    const float* lin2W = (const float*)d_in[13];
    const float* lin2b = (const float*)d_in[14];
    float* out = (float*)d_out;

    void *aggp, *xp;
    cudaGetSymbolAddress(&aggp, g_agg_h);
    cudaGetSymbolAddress(&xp,   g_x_h);

    const int ROWT  = (NN + 127) / 128;           // 391
    const int NB    = (NN + 255) / 256;           // 196
    const int EB5   = (EE + 511) / 512;           // 1563
    const int WARPB = (NN * 32 + 255) / 256;      // 6250 (one warp per node)

    const float* nfc = nullptr;
    void*        nv  = nullptr;

    // ---- layer-1 feat GEMM first (TRIG=true: fires early so k_hist overlaps) ----
    pdl_launch(dim3(ROWT, 2), dim3(256), gemm_mma<128, 128, true, true, false, false>,
               (const void*)h, W1, nfc, nv, (int)NN, 0, al1, ar1);

    // ---- CSR build (hist overlaps gemm1; rest is a dependent chain) ----
    pdl_launch(dim3(EB5), dim3(512), k_hist, dst);
    pdl_launch(dim3(98), dim3(512), k_scan1);
    pdl_launch(dim3(NB), dim3(256), k_scan23);
    pdl_launch(dim3(EB5), dim3(512), k_scatter, src, dst);

    // ---- layer 1 aggregation + lin ----
    pdl_launch(dim3(WARPB), dim3(256), gat_agg, b1);
    pdl_launch(dim3(ROWT, 1), dim3(256), gemm_mma<128, 64, false, false, true, true>,
               (const void*)aggp, lin1W, lin1b, xp, (int)NN, 1, nfc, nfc);

    // ---- layer 2 ----
    pdl_launch(dim3(ROWT, 2), dim3(256), gemm_mma<64, 128, true, false, true, false>,
               (const void*)xp, W2, nfc, nv, (int)NN, 0, al2, ar2);
    pdl_launch(dim3(WARPB), dim3(256), gat_agg, b2);
    pdl_launch(dim3(ROWT, 1), dim3(256), gemm_mma<128, 64, false, false, true, false>,
               (const void*)aggp, lin2W, lin2b, (void*)out, (int)NN, 0, nfc, nfc);
}

// round 16
// speedup vs baseline: 1.0446x; 1.0147x over previous
#include <cuda_runtime.h>
#include <cuda_fp16.h>
#include <cuda_bf16.h>

#define NN 50000
#define EE 800000

// ---------------- scratch (no allocations allowed) ----------------
__device__ __half2 g_feat_h[NN * 64];   // ATTN fc output, fp16 [N, 128]
__device__ __half2 g_agg_h [NN * 64];   // conv output (agg+bias), fp16 [N, 128]
__device__ __half2 g_x_h   [NN * 32];   // layer-1 lin+relu output, fp16 [N, 64]
__device__ float g_el  [NN * 2];
__device__ float g_er  [NN * 2];
// CSR scratch (g_cnt is zero at load; k_scan23 re-zeros it after use)
__device__ int g_cnt[NN];
__device__ int g_tmp[NN];
__device__ int g_rowptr[NN + 1];
__device__ int g_rank[EE];           // within-bucket rank per edge (from k_hist)
__device__ int g_srcs[EE];
__device__ int g_bsum[128];

// ---------------- helpers ----------------
__device__ __forceinline__ unsigned f2tf(float x) {
    unsigned u;
    asm("cvt.rna.tf32.f32 %0, %1;" : "=r"(u) : "f"(x));
    return u;
}
__device__ __forceinline__ void pdl_wait() {
    cudaGridDependencySynchronize();
}
// warp-inclusive scan (32 lanes)
__device__ __forceinline__ int warp_iscan(int x, int lane) {
    #pragma unroll
    for (int off = 1; off < 32; off <<= 1) {
        int t = __shfl_up_sync(0xffffffffu, x, off);
        if (lane >= off) x += t;
    }
    return x;
}

// ======================= tf32 tensor-core GEMM (+ fused attn logits) ==========
// C[n,M] = A[n,K] @ W[K,M] (+bias,+relu). 128x64 tile, 256 thr, m16n8k8 mma.
// AHALF: A is fp16 (__half row-major). CHALF: C written as fp16.
// ATTN: M==128, blockIdx.y == head; epilogue writes fp16 feat + g_el/g_er.
// TRIG: fire programmatic-launch trigger early (next kernel is independent).
template<int K, int M, bool ATTN, bool TRIG, bool AHALF, bool CHALF>
__global__ void __launch_bounds__(256)
gemm_mma(const void* __restrict__ Av, const float* __restrict__ W,
         const float* __restrict__ bias, void* __restrict__ Cv,
         int n, int relu, const float* __restrict__ al, const float* __restrict__ ar) {
    pdl_wait();
    if (TRIG) cudaTriggerProgrammaticLaunchCompletion();
    __shared__ float As[128][36];
    __shared__ float Ws[32][72];
    const float* Af = (const float*)Av;
    const __half* Ah = (const __half*)Av;
    int tid  = threadIdx.x;
    int lane = tid & 31, warp = tid >> 5;
    int g = lane >> 2, t4 = lane & 3;
    int r0 = blockIdx.x * 128;
    int c0 = blockIdx.y * 64;

    float acc[8][4];
    #pragma unroll
    for (int i = 0; i < 8; i++)
        #pragma unroll
        for (int j = 0; j < 4; j++) acc[i][j] = 0.f;

    float4 va[4]; uint2 vah[4]; float4 vw[2];

    #pragma unroll
    for (int it = 0; it < 4; it++) {
        int f4 = tid + it * 256;
        int row = f4 >> 3, kq = (f4 & 7) * 4;
        if (AHALF) {
            vah[it] = make_uint2(0u, 0u);
            if (r0 + row < n) vah[it] = *(const uint2*)&Ah[(size_t)(r0 + row) * K + kq];
        } else {
            va[it] = make_float4(0.f, 0.f, 0.f, 0.f);
            if (r0 + row < n) va[it] = *(const float4*)&Af[(size_t)(r0 + row) * K + kq];
        }
    }
    #pragma unroll
    for (int it = 0; it < 2; it++) {
        int f4 = tid + it * 256;
        int k = f4 >> 4, cq = (f4 & 15) * 4;
        vw[it] = *(const float4*)&W[(size_t)k * M + c0 + cq];
    }

    for (int kc = 0; kc < K; kc += 32) {
        #pragma unroll
        for (int it = 0; it < 4; it++) {
            int f4 = tid + it * 256;
            int row = f4 >> 3, kq = (f4 & 7) * 4;
            if (AHALF) {
                float2 p0 = __half22float2(*(const __half2*)&vah[it].x);
                float2 p1 = __half22float2(*(const __half2*)&vah[it].y);
                As[row][kq + 0] = p0.x;
                As[row][kq + 1] = p0.y;
                As[row][kq + 2] = p1.x;
                As[row][kq + 3] = p1.y;
            } else {
                As[row][kq + 0] = __uint_as_float(f2tf(va[it].x));
                As[row][kq + 1] = __uint_as_float(f2tf(va[it].y));
                As[row][kq + 2] = __uint_as_float(f2tf(va[it].z));
                As[row][kq + 3] = __uint_as_float(f2tf(va[it].w));
            }
        }
        #pragma unroll
        for (int it = 0; it < 2; it++) {
            int f4 = tid + it * 256;
            int k = f4 >> 4, cq = (f4 & 15) * 4;
            Ws[k][cq + 0] = __uint_as_float(f2tf(vw[it].x));
            Ws[k][cq + 1] = __uint_as_float(f2tf(vw[it].y));
            Ws[k][cq + 2] = __uint_as_float(f2tf(vw[it].z));
            Ws[k][cq + 3] = __uint_as_float(f2tf(vw[it].w));
        }
        __syncthreads();

        if (kc + 32 < K) {
            #pragma unroll
            for (int it = 0; it < 4; it++) {
                int f4 = tid + it * 256;
                int row = f4 >> 3, kq = (f4 & 7) * 4;
                if (AHALF) {
                    vah[it] = make_uint2(0u, 0u);
                    if (r0 + row < n)
                        vah[it] = *(const uint2*)&Ah[(size_t)(r0 + row) * K + kc + 32 + kq];
                } else {
                    va[it] = make_float4(0.f, 0.f, 0.f, 0.f);
                    if (r0 + row < n)
                        va[it] = *(const float4*)&Af[(size_t)(r0 + row) * K + kc + 32 + kq];
                }
            }
            #pragma unroll
            for (int it = 0; it < 2; it++) {
                int f4 = tid + it * 256;
                int k = f4 >> 4, cq = (f4 & 15) * 4;
                vw[it] = *(const float4*)&W[(size_t)(kc + 32 + k) * M + c0 + cq];
            }
        }

        int wr = warp * 16;
        #pragma unroll
        for (int kk = 0; kk < 4; kk++) {
            unsigned a0 = __float_as_uint(As[wr + g    ][kk * 8 + t4    ]);
            unsigned a1 = __float_as_uint(As[wr + g + 8][kk * 8 + t4    ]);
            unsigned a2 = __float_as_uint(As[wr + g    ][kk * 8 + t4 + 4]);
            unsigned a3 = __float_as_uint(As[wr + g + 8][kk * 8 + t4 + 4]);
            #pragma unroll
            for (int nt = 0; nt < 8; nt++) {
                unsigned b0 = __float_as_uint(Ws[kk * 8 + t4    ][nt * 8 + g]);
                unsigned b1 = __float_as_uint(Ws[kk * 8 + t4 + 4][nt * 8 + g]);
                asm volatile(
                    "mma.sync.aligned.m16n8k8.row.col.f32.tf32.tf32.f32 "
                    "{%0,%1,%2,%3}, {%4,%5,%6,%7}, {%8,%9}, {%0,%1,%2,%3};"
                    : "+f"(acc[nt][0]), "+f"(acc[nt][1]),
                      "+f"(acc[nt][2]), "+f"(acc[nt][3])
                    : "r"(a0), "r"(a1), "r"(a2), "r"(a3), "r"(b0), "r"(b1));
            }
        }
        __syncthreads();
    }

    int wr = warp * 16;
    float el0 = 0.f, er0 = 0.f, el1 = 0.f, er1 = 0.f;
    int head = blockIdx.y;
    #pragma unroll
    for (int nt = 0; nt < 8; nt++) {
        int col = c0 + nt * 8 + t4 * 2;
        float bx = 0.f, by = 0.f;
        if (bias) { bx = bias[col]; by = bias[col + 1]; }
        float v0 = acc[nt][0] + bx, v1 = acc[nt][1] + by;
        float v2 = acc[nt][2] + bx, v3 = acc[nt][3] + by;
        if (relu) {
            v0 = fmaxf(v0, 0.f); v1 = fmaxf(v1, 0.f);
            v2 = fmaxf(v2, 0.f); v3 = fmaxf(v3, 0.f);
        }
        int row0 = r0 + wr + g, row1 = row0 + 8;
        if (ATTN) {
            int lc = head * 64 + nt * 8 + t4 * 2;
            float a0 = al[lc], a1 = al[lc + 1];
            float q0 = ar[lc], q1 = ar[lc + 1];
            el0 = fmaf(v0, a0, fmaf(v1, a1, el0));
            er0 = fmaf(v0, q0, fmaf(v1, q1, er0));
            el1 = fmaf(v2, a0, fmaf(v3, a1, el1));
            er1 = fmaf(v2, q0, fmaf(v3, q1, er1));
            int hc = head * 32 + nt * 4 + t4;
            if (row0 < n) g_feat_h[(size_t)row0 * 64 + hc] = __floats2half2_rn(v0, v1);
            if (row1 < n) g_feat_h[(size_t)row1 * 64 + hc] = __floats2half2_rn(v2, v3);
        } else if (CHALF) {
            __half2* Ch = (__half2*)Cv;
            if (row0 < n) Ch[((size_t)row0 * M + col) >> 1] = __floats2half2_rn(v0, v1);
            if (row1 < n) Ch[((size_t)row1 * M + col) >> 1] = __floats2half2_rn(v2, v3);
        } else {
            float* Cf = (float*)Cv;
            if (row0 < n) *(float2*)&Cf[(size_t)row0 * M + col] = make_float2(v0, v1);
            if (row1 < n) *(float2*)&Cf[(size_t)row1 * M + col] = make_float2(v2, v3);
        }
    }
    if (ATTN) {
        #pragma unroll
        for (int o = 1; o <= 2; o <<= 1) {
            el0 += __shfl_xor_sync(0xffffffffu, el0, o);
            er0 += __shfl_xor_sync(0xffffffffu, er0, o);
            el1 += __shfl_xor_sync(0xffffffffu, el1, o);
            er1 += __shfl_xor_sync(0xffffffffu, er1, o);
        }
        if (t4 == 0) {
            int row0 = r0 + wr + g, row1 = row0 + 8;
            if (row0 < n) { g_el[row0 * 2 + head] = el0; g_er[row0 * 2 + head] = er0; }
            if (row1 < n) { g_el[row1 * 2 + head] = el1; g_er[row1 * 2 + head] = er1; }
        }
    }
}

// ======================= CSR build =======================
// hist runs CONCURRENTLY with the layer-1 ATTN GEMM (no grid sync: it reads
// only the dst input and g_cnt, which the previous call's k_scan23 re-zeroed).
__global__ void __launch_bounds__(512) k_hist(const int* __restrict__ dst) {
    int e = blockIdx.x * blockDim.x + threadIdx.x;
    if (e < EE) {
        int p = atomicAdd(&g_cnt[dst[e]], 1);
        g_rank[e] = p;
    }
}
// 98 blocks x 512: per-block inclusive scans, warp-shuffle based (2 barriers)
__global__ void __launch_bounds__(512) k_scan1() {
    pdl_wait();
    __shared__ int wsum[16];
    int tid = threadIdx.x, lane = tid & 31, wid = tid >> 5;
    int i = blockIdx.x * 512 + tid;
    int v = (i < NN) ? g_cnt[i] : 0;
    int x = warp_iscan(v, lane);                 // inclusive within warp
    if (lane == 31) wsum[wid] = x;
    __syncthreads();
    if (wid == 0) {
        int s = (lane < 16) ? wsum[lane] : 0;
        s = warp_iscan(s, lane);
        if (lane < 16) wsum[lane] = s;           // inclusive scan of warp totals
    }
    __syncthreads();
    int base = (wid > 0) ? wsum[wid - 1] : 0;
    int incl = base + x;
    if (i < NN) g_tmp[i] = incl;
    if (tid == 511) g_bsum[blockIdx.x] = incl;   // block total
}
// scan2+scan3 merged, warp-shuffle based: every block redundantly scans the 98
// block sums, then finalizes rowptr and restores g_cnt = 0. (2 barriers)
__global__ void __launch_bounds__(256) k_scan23() {
    pdl_wait();
    __shared__ int sb[128];
    __shared__ int wtot[4];
    int tid = threadIdx.x, lane = tid & 31, wid = tid >> 5;
    if (wid < 4) {
        int t = wid * 32 + lane;
        int v = (t < 98) ? g_bsum[t] : 0;
        int x = warp_iscan(v, lane);
        sb[t] = x;
        if (lane == 31) wtot[wid] = x;
    }
    __syncthreads();
    int i = blockIdx.x * blockDim.x + tid;
    if (i >= NN) return;
    int j = i >> 9;
    int off = 0;
    if (j > 0) {
        int jw = (j - 1) >> 5;
        off = sb[j - 1];
        #pragma unroll
        for (int k = 0; k < 4; k++)
            if (k < jw) off += wtot[k];
    }
    int excl = g_tmp[i] - g_cnt[i] + off;
    g_rowptr[i] = excl;
    g_cnt[i]    = 0;                 // restore invariant: g_cnt==0 at next call
    if (i == NN - 1) g_rowptr[NN] = g_tmp[i] + off;
}
// atomic-free scatter: position = rowptr[dst] + rank (recorded by k_hist)
__global__ void __launch_bounds__(512) k_scatter(const int* __restrict__ src,
                                                 const int* __restrict__ dst) {
    pdl_wait();
    int e = blockIdx.x * blockDim.x + threadIdx.x;
    if (e >= EE) return;
    int d = dst[e];
    g_srcs[g_rowptr[d] + g_rank[e]] = src[e];
}

// ======================= fused edge-softmax + aggregation =======================
// one warp per dst node, TWO edges per warp-step: lanes 0-15 take edge j,
// lanes 16-31 take edge j+1; each lane loads a uint4 (8 cols) so a half-warp
// covers the full 128-col row. Halves the dependent-load chain vs 1 edge/step.
// fp32 accumulate, fp16 output (g_agg_h).
__global__ void __launch_bounds__(256)
gat_agg(const float* __restrict__ bias) {
    pdl_wait();
    __shared__ float2 s_ex[8][32];
    __shared__ int    s_src[8][32];
    int lane = threadIdx.x & 31, w = threadIdx.x >> 5;
    int d = blockIdx.x * 8 + w;
    if (d >= NN) return;
    int beg = g_rowptr[d], end = g_rowptr[d + 1];
    float2 er2 = *(const float2*)(g_er + 2 * d);
    const uint4* feat4 = (const uint4*)g_feat_h;   // 16B = 8 halves per lane
    int hl  = lane & 15;         // half-lane: covers cols 8*hl .. 8*hl+7
    int sub = lane >> 4;         // 0 -> even edges, 1 -> odd edges

    float acc[8];
    #pragma unroll
    for (int i = 0; i < 8; i++) acc[i] = 0.f;
    float z0 = 0.f, z1 = 0.f;

    for (int c = beg; c < end; c += 32) {
        int idx = c + lane;
        bool valid = idx < end;
        int s = valid ? g_srcs[idx] : 0;
        float2 el2 = *(const float2*)(g_el + 2 * s);
        float e0 = el2.x + er2.x; e0 = e0 > 0.f ? e0 : 0.2f * e0;
        float e1 = el2.y + er2.y; e1 = e1 > 0.f ? e1 : 0.2f * e1;
        float x0 = valid ? __expf(e0) : 0.f;
        float x1 = valid ? __expf(e1) : 0.f;
        z0 += x0; z1 += x1;
        s_ex[w][lane]  = make_float2(x0, x1);     // entries >= m carry ex = 0
        s_src[w][lane] = s;
        __syncwarp();
        int m = min(32, end - c);
        #pragma unroll 4
        for (int j = 0; j < m; j += 2) {
            int jj = j + sub;                     // <= 31; ex=0 pads odd tails
            int sj = s_src[w][jj];
            float2 exj = s_ex[w][jj];
            float wgt = (hl < 8) ? exj.x : exj.y; // cols<64 head0, else head1
            uint4 u = feat4[(size_t)sj * 16 + hl];
            float2 fa = __half22float2(*(const __half2*)&u.x);
            float2 fb = __half22float2(*(const __half2*)&u.y);
            float2 fc = __half22float2(*(const __half2*)&u.z);
            float2 fd = __half22float2(*(const __half2*)&u.w);
            acc[0] = fmaf(wgt, fa.x, acc[0]);
            acc[1] = fmaf(wgt, fa.y, acc[1]);
            acc[2] = fmaf(wgt, fb.x, acc[2]);
            acc[3] = fmaf(wgt, fb.y, acc[3]);
            acc[4] = fmaf(wgt, fc.x, acc[4]);
            acc[5] = fmaf(wgt, fc.y, acc[5]);
            acc[6] = fmaf(wgt, fd.x, acc[6]);
            acc[7] = fmaf(wgt, fd.y, acc[7]);
        }
        __syncwarp();
    }
    #pragma unroll
    for (int o = 16; o > 0; o >>= 1) {
        z0 += __shfl_xor_sync(0xffffffffu, z0, o);
        z1 += __shfl_xor_sync(0xffffffffu, z1, o);
    }
    // combine the two half-warps (even-edge + odd-edge partial sums)
    #pragma unroll
    for (int i = 0; i < 8; i++)
        acc[i] += __shfl_xor_sync(0xffffffffu, acc[i], 16);

    float z = (hl < 8) ? z0 : z1;
    float ia = (z > 0.f) ? __fdividef(1.f, z) : 0.f;
    if (sub == 0) {
        float4 ba = ((const float4*)bias)[2 * hl];
        float4 bb = ((const float4*)bias)[2 * hl + 1];
        __half2 h0 = __floats2half2_rn(fmaf(acc[0], ia, ba.x), fmaf(acc[1], ia, ba.y));
        __half2 h1 = __floats2half2_rn(fmaf(acc[2], ia, ba.z), fmaf(acc[3], ia, ba.w));
        __half2 h2 = __floats2half2_rn(fmaf(acc[4], ia, bb.x), fmaf(acc[5], ia, bb.y));
        __half2 h3 = __floats2half2_rn(fmaf(acc[6], ia, bb.z), fmaf(acc[7], ia, bb.w));
        uint4 outw;
        outw.x = *(unsigned*)&h0;
        outw.y = *(unsigned*)&h1;
        outw.z = *(unsigned*)&h2;
        outw.w = *(unsigned*)&h3;
        ((uint4*)g_agg_h)[(size_t)d * 16 + hl] = outw;
    }
}

// ======================= host =======================
template<typename... Args>
static inline void pdl_launch(dim3 gd, dim3 bd, void (*kfn)(Args...), Args... args) {
    cudaLaunchConfig_t cfg = {};
    cfg.gridDim = gd;
    cfg.blockDim = bd;
    cudaLaunchAttribute at[1];
    at[0].id = cudaLaunchAttributeProgrammaticStreamSerialization;
    at[0].val.programmaticStreamSerializationAllowed = 1;
    cfg.attrs = at;
    cfg.numAttrs = 1;
    cudaLaunchKernelEx(&cfg, kfn, args...);
}

extern "C" void kernel_launch(void* const* d_in, const int* in_sizes, int n_in,
                              void* d_out, int out_size) {
    const float* h     = (const float*)d_in[0];
    const int*   src   = (const int*)d_in[1];
    const int*   dst   = (const int*)d_in[2];
    const float* W1    = (const float*)d_in[3];
    const float* al1   = (const float*)d_in[4];
    const float* ar1   = (const float*)d_in[5];
    const float* b1    = (const float*)d_in[6];
    const float* lin1W = (const float*)d_in[7];
    const float* lin1b = (const float*)d_in[8];
    const float* W2    = (const float*)d_in[9];
    const float* al2   = (const float*)d_in[10];
    const float* ar2   = (const float*)d_in[11];
    const float* b2    = (const float*)d_in[12];
    const float* lin2W = (const float*)d_in[13];
    const float* lin2b = (const float*)d_in[14];
    float* out = (float*)d_out;

    void *aggp, *xp;
    cudaGetSymbolAddress(&aggp, g_agg_h);
    cudaGetSymbolAddress(&xp,   g_x_h);

    const int ROWT  = (NN + 127) / 128;           // 391
    const int NB    = (NN + 255) / 256;           // 196
    const int EB5   = (EE + 511) / 512;           // 1563
    const int WARPB = (NN * 32 + 255) / 256;      // 6250 (one warp per node)

    const float* nfc = nullptr;
    void*        nv  = nullptr;

    // ---- layer-1 feat GEMM first (TRIG=true: fires early so k_hist overlaps) ----
    pdl_launch(dim3(ROWT, 2), dim3(256), gemm_mma<128, 128, true, true, false, false>,
               (const void*)h, W1, nfc, nv, (int)NN, 0, al1, ar1);

    // ---- CSR build (hist overlaps gemm1; rest is a dependent chain) ----
    pdl_launch(dim3(EB5), dim3(512), k_hist, dst);
    pdl_launch(dim3(98), dim3(512), k_scan1);
    pdl_launch(dim3(NB), dim3(256), k_scan23);
    pdl_launch(dim3(EB5), dim3(512), k_scatter, src, dst);

    // ---- layer 1 aggregation + lin ----
    pdl_launch(dim3(WARPB), dim3(256), gat_agg, b1);
    pdl_launch(dim3(ROWT, 1), dim3(256), gemm_mma<128, 64, false, false, true, true>,
               (const void*)aggp, lin1W, lin1b, xp, (int)NN, 1, nfc, nfc);

    // ---- layer 2 ----
    pdl_launch(dim3(ROWT, 2), dim3(256), gemm_mma<64, 128, true, false, true, false>,
               (const void*)xp, W2, nfc, nv, (int)NN, 0, al2, ar2);
    pdl_launch(dim3(WARPB), dim3(256), gat_agg, b2);
    pdl_launch(dim3(ROWT, 1), dim3(256), gemm_mma<128, 64, false, false, true, false>,
               (const void*)aggp, lin2W, lin2b, (void*)out, (int)NN, 0, nfc, nfc);
}

// round 17
// speedup vs baseline: 1.0463x; 1.0016x over previous
#include <cuda_runtime.h>
#include <cuda_fp16.h>
#include <cuda_bf16.h>

#define NN 50000
#define EE 800000

// ---------------- scratch (no allocations allowed) ----------------
__device__ __half2 g_feat_h[NN * 64];   // ATTN fc output, fp16 [N, 128]
__device__ __half2 g_agg_h [NN * 64];   // conv output (agg+bias), fp16 [N, 128]
__device__ __half2 g_x_h   [NN * 32];   // layer-1 lin+relu output, fp16 [N, 64]
__device__ float g_el  [NN * 2];
__device__ float g_er  [NN * 2];
// CSR scratch (g_cnt is zero at load; k_scan23 re-zeros it after use)
__device__ int g_cnt[NN];
__device__ int g_tmp[NN];
__device__ int g_rowptr[NN + 1];
__device__ int g_rank[EE];           // within-bucket rank per edge (from k_hist)
__device__ int g_srcs[EE];
__device__ int g_bsum[128];

// ---------------- helpers ----------------
__device__ __forceinline__ unsigned f2tf(float x) {
    unsigned u;
    asm("cvt.rna.tf32.f32 %0, %1;" : "=r"(u) : "f"(x));
    return u;
}
__device__ __forceinline__ void pdl_wait() {
    cudaGridDependencySynchronize();
}
// warp-inclusive scan (32 lanes)
__device__ __forceinline__ int warp_iscan(int x, int lane) {
    #pragma unroll
    for (int off = 1; off < 32; off <<= 1) {
        int t = __shfl_up_sync(0xffffffffu, x, off);
        if (lane >= off) x += t;
    }
    return x;
}

// ======================= tf32 tensor-core GEMM (+ fused attn logits) ==========
// C[n,M] = A[n,K] @ W[K,M] (+bias,+relu). 128x64 tile, 256 thr, m16n8k8 mma.
// AHALF: A is fp16 (__half row-major). CHALF: C written as fp16.
// ATTN: M==128, blockIdx.y == head; epilogue writes fp16 feat + g_el/g_er.
// TRIG: fire programmatic-launch trigger early (next kernel is independent).
template<int K, int M, bool ATTN, bool TRIG, bool AHALF, bool CHALF>
__global__ void __launch_bounds__(256)
gemm_mma(const void* __restrict__ Av, const float* __restrict__ W,
         const float* __restrict__ bias, void* __restrict__ Cv,
         int n, int relu, const float* __restrict__ al, const float* __restrict__ ar) {
    pdl_wait();
    if (TRIG) cudaTriggerProgrammaticLaunchCompletion();
    __shared__ float As[128][36];
    __shared__ float Ws[32][72];
    const float* Af = (const float*)Av;
    const __half* Ah = (const __half*)Av;
    int tid  = threadIdx.x;
    int lane = tid & 31, warp = tid >> 5;
    int g = lane >> 2, t4 = lane & 3;
    int r0 = blockIdx.x * 128;
    int c0 = blockIdx.y * 64;

    float acc[8][4];
    #pragma unroll
    for (int i = 0; i < 8; i++)
        #pragma unroll
        for (int j = 0; j < 4; j++) acc[i][j] = 0.f;

    float4 va[4]; uint2 vah[4]; float4 vw[2];

    #pragma unroll
    for (int it = 0; it < 4; it++) {
        int f4 = tid + it * 256;
        int row = f4 >> 3, kq = (f4 & 7) * 4;
        if (AHALF) {
            vah[it] = make_uint2(0u, 0u);
            if (r0 + row < n) vah[it] = *(const uint2*)&Ah[(size_t)(r0 + row) * K + kq];
        } else {
            va[it] = make_float4(0.f, 0.f, 0.f, 0.f);
            if (r0 + row < n) va[it] = *(const float4*)&Af[(size_t)(r0 + row) * K + kq];
        }
    }
    #pragma unroll
    for (int it = 0; it < 2; it++) {
        int f4 = tid + it * 256;
        int k = f4 >> 4, cq = (f4 & 15) * 4;
        vw[it] = *(const float4*)&W[(size_t)k * M + c0 + cq];
    }

    for (int kc = 0; kc < K; kc += 32) {
        #pragma unroll
        for (int it = 0; it < 4; it++) {
            int f4 = tid + it * 256;
            int row = f4 >> 3, kq = (f4 & 7) * 4;
            if (AHALF) {
                float2 p0 = __half22float2(*(const __half2*)&vah[it].x);
                float2 p1 = __half22float2(*(const __half2*)&vah[it].y);
                As[row][kq + 0] = p0.x;
                As[row][kq + 1] = p0.y;
                As[row][kq + 2] = p1.x;
                As[row][kq + 3] = p1.y;
            } else {
                As[row][kq + 0] = __uint_as_float(f2tf(va[it].x));
                As[row][kq + 1] = __uint_as_float(f2tf(va[it].y));
                As[row][kq + 2] = __uint_as_float(f2tf(va[it].z));
                As[row][kq + 3] = __uint_as_float(f2tf(va[it].w));
            }
        }
        #pragma unroll
        for (int it = 0; it < 2; it++) {
            int f4 = tid + it * 256;
            int k = f4 >> 4, cq = (f4 & 15) * 4;
            Ws[k][cq + 0] = __uint_as_float(f2tf(vw[it].x));
            Ws[k][cq + 1] = __uint_as_float(f2tf(vw[it].y));
            Ws[k][cq + 2] = __uint_as_float(f2tf(vw[it].z));
            Ws[k][cq + 3] = __uint_as_float(f2tf(vw[it].w));
        }
        __syncthreads();

        if (kc + 32 < K) {
            #pragma unroll
            for (int it = 0; it < 4; it++) {
                int f4 = tid + it * 256;
                int row = f4 >> 3, kq = (f4 & 7) * 4;
                if (AHALF) {
                    vah[it] = make_uint2(0u, 0u);
                    if (r0 + row < n)
                        vah[it] = *(const uint2*)&Ah[(size_t)(r0 + row) * K + kc + 32 + kq];
                } else {
                    va[it] = make_float4(0.f, 0.f, 0.f, 0.f);
                    if (r0 + row < n)
                        va[it] = *(const float4*)&Af[(size_t)(r0 + row) * K + kc + 32 + kq];
                }
            }
            #pragma unroll
            for (int it = 0; it < 2; it++) {
                int f4 = tid + it * 256;
                int k = f4 >> 4, cq = (f4 & 15) * 4;
                vw[it] = *(const float4*)&W[(size_t)(kc + 32 + k) * M + c0 + cq];
            }
        }

        int wr = warp * 16;
        #pragma unroll
        for (int kk = 0; kk < 4; kk++) {
            unsigned a0 = __float_as_uint(As[wr + g    ][kk * 8 + t4    ]);
            unsigned a1 = __float_as_uint(As[wr + g + 8][kk * 8 + t4    ]);
            unsigned a2 = __float_as_uint(As[wr + g    ][kk * 8 + t4 + 4]);
            unsigned a3 = __float_as_uint(As[wr + g + 8][kk * 8 + t4 + 4]);
            #pragma unroll
            for (int nt = 0; nt < 8; nt++) {
                unsigned b0 = __float_as_uint(Ws[kk * 8 + t4    ][nt * 8 + g]);
                unsigned b1 = __float_as_uint(Ws[kk * 8 + t4 + 4][nt * 8 + g]);
                asm volatile(
                    "mma.sync.aligned.m16n8k8.row.col.f32.tf32.tf32.f32 "
                    "{%0,%1,%2,%3}, {%4,%5,%6,%7}, {%8,%9}, {%0,%1,%2,%3};"
                    : "+f"(acc[nt][0]), "+f"(acc[nt][1]),
                      "+f"(acc[nt][2]), "+f"(acc[nt][3])
                    : "r"(a0), "r"(a1), "r"(a2), "r"(a3), "r"(b0), "r"(b1));
            }
        }
        __syncthreads();
    }

    int wr = warp * 16;
    float el0 = 0.f, er0 = 0.f, el1 = 0.f, er1 = 0.f;
    int head = blockIdx.y;
    #pragma unroll
    for (int nt = 0; nt < 8; nt++) {
        int col = c0 + nt * 8 + t4 * 2;
        float bx = 0.f, by = 0.f;
        if (bias) { bx = bias[col]; by = bias[col + 1]; }
        float v0 = acc[nt][0] + bx, v1 = acc[nt][1] + by;
        float v2 = acc[nt][2] + bx, v3 = acc[nt][3] + by;
        if (relu) {
            v0 = fmaxf(v0, 0.f); v1 = fmaxf(v1, 0.f);
            v2 = fmaxf(v2, 0.f); v3 = fmaxf(v3, 0.f);
        }
        int row0 = r0 + wr + g, row1 = row0 + 8;
        if (ATTN) {
            int lc = head * 64 + nt * 8 + t4 * 2;
            float a0 = al[lc], a1 = al[lc + 1];
            float q0 = ar[lc], q1 = ar[lc + 1];
            el0 = fmaf(v0, a0, fmaf(v1, a1, el0));
            er0 = fmaf(v0, q0, fmaf(v1, q1, er0));
            el1 = fmaf(v2, a0, fmaf(v3, a1, el1));
            er1 = fmaf(v2, q0, fmaf(v3, q1, er1));
            int hc = head * 32 + nt * 4 + t4;
            if (row0 < n) g_feat_h[(size_t)row0 * 64 + hc] = __floats2half2_rn(v0, v1);
            if (row1 < n) g_feat_h[(size_t)row1 * 64 + hc] = __floats2half2_rn(v2, v3);
        } else if (CHALF) {
            __half2* Ch = (__half2*)Cv;
            if (row0 < n) Ch[((size_t)row0 * M + col) >> 1] = __floats2half2_rn(v0, v1);
            if (row1 < n) Ch[((size_t)row1 * M + col) >> 1] = __floats2half2_rn(v2, v3);
        } else {
            float* Cf = (float*)Cv;
            if (row0 < n) *(float2*)&Cf[(size_t)row0 * M + col] = make_float2(v0, v1);
            if (row1 < n) *(float2*)&Cf[(size_t)row1 * M + col] = make_float2(v2, v3);
        }
    }
    if (ATTN) {
        #pragma unroll
        for (int o = 1; o <= 2; o <<= 1) {
            el0 += __shfl_xor_sync(0xffffffffu, el0, o);
            er0 += __shfl_xor_sync(0xffffffffu, er0, o);
            el1 += __shfl_xor_sync(0xffffffffu, el1, o);
            er1 += __shfl_xor_sync(0xffffffffu, er1, o);
        }
        if (t4 == 0) {
            int row0 = r0 + wr + g, row1 = row0 + 8;
            if (row0 < n) { g_el[row0 * 2 + head] = el0; g_er[row0 * 2 + head] = er0; }
            if (row1 < n) { g_el[row1 * 2 + head] = el1; g_er[row1 * 2 + head] = er1; }
        }
    }
}

// ======================= CSR build =======================
// hist runs CONCURRENTLY with the layer-1 ATTN GEMM (no grid sync: it reads
// only the dst input and g_cnt, which the previous call's k_scan23 re-zeroed).
__global__ void __launch_bounds__(512) k_hist(const int* __restrict__ dst) {
    int e = blockIdx.x * blockDim.x + threadIdx.x;
    if (e < EE) {
        int p = atomicAdd(&g_cnt[dst[e]], 1);
        g_rank[e] = p;
    }
}
// 98 blocks x 512: per-block inclusive scans, warp-shuffle based (2 barriers)
__global__ void __launch_bounds__(512) k_scan1() {
    pdl_wait();
    __shared__ int wsum[16];
    int tid = threadIdx.x, lane = tid & 31, wid = tid >> 5;
    int i = blockIdx.x * 512 + tid;
    int v = (i < NN) ? g_cnt[i] : 0;
    int x = warp_iscan(v, lane);                 // inclusive within warp
    if (lane == 31) wsum[wid] = x;
    __syncthreads();
    if (wid == 0) {
        int s = (lane < 16) ? wsum[lane] : 0;
        s = warp_iscan(s, lane);
        if (lane < 16) wsum[lane] = s;           // inclusive scan of warp totals
    }
    __syncthreads();
    int base = (wid > 0) ? wsum[wid - 1] : 0;
    int incl = base + x;
    if (i < NN) g_tmp[i] = incl;
    if (tid == 511) g_bsum[blockIdx.x] = incl;   // block total
}
// scan2+scan3 merged, warp-shuffle based; TWO consecutive nodes per thread
// (int2 loads/stores; both nodes share the same 512-block index j).
__global__ void __launch_bounds__(256) k_scan23() {
    pdl_wait();
    __shared__ int sb[128];
    __shared__ int wtot[4];
    int tid = threadIdx.x, lane = tid & 31, wid = tid >> 5;
    if (wid < 4) {
        int t = wid * 32 + lane;
        int v = (t < 98) ? g_bsum[t] : 0;
        int x = warp_iscan(v, lane);
        sb[t] = x;
        if (lane == 31) wtot[wid] = x;
    }
    __syncthreads();
    int i = (blockIdx.x * blockDim.x + tid) * 2;   // even; pair (i, i+1)
    if (i >= NN) return;
    int j = i >> 9;                                // same for both pair elems
    int off = 0;
    if (j > 0) {
        int jw = (j - 1) >> 5;
        off = sb[j - 1];
        #pragma unroll
        for (int k = 0; k < 4; k++)
            if (k < jw) off += wtot[k];
    }
    int2 tmp2 = *(const int2*)&g_tmp[i];
    int2 cnt2 = *(const int2*)&g_cnt[i];
    int2 rp;
    rp.x = tmp2.x - cnt2.x + off;
    rp.y = tmp2.y - cnt2.y + off;
    *(int2*)&g_rowptr[i] = rp;
    *(int2*)&g_cnt[i] = make_int2(0, 0);           // restore invariant
    if (i + 1 == NN - 1) g_rowptr[NN] = tmp2.y + off;
}
// atomic-free scatter: position = rowptr[dst] + rank (recorded by k_hist).
// TWO edges per thread (e, e + EE/2) for doubled MLP; both halves coalesced.
__global__ void __launch_bounds__(512) k_scatter(const int* __restrict__ src,
                                                 const int* __restrict__ dst) {
    pdl_wait();
    int e = blockIdx.x * blockDim.x + threadIdx.x;
    if (e >= EE / 2) return;
    int e2 = e + EE / 2;
    int d1 = dst[e],  r1 = g_rank[e];
    int d2 = dst[e2], r2 = g_rank[e2];
    int p1 = g_rowptr[d1] + r1;
    int p2 = g_rowptr[d2] + r2;
    g_srcs[p1] = src[e];
    g_srcs[p2] = src[e2];
}

// ======================= fused edge-softmax + aggregation =======================
// one warp per dst node, TWO edges per warp-step: lanes 0-15 take edge j,
// lanes 16-31 take edge j+1; each lane loads a uint4 (8 cols) so a half-warp
// covers the full 128-col row. fp32 accumulate, fp16 output (g_agg_h).
__global__ void __launch_bounds__(256)
gat_agg(const float* __restrict__ bias) {
    pdl_wait();
    __shared__ float2 s_ex[8][32];
    __shared__ int    s_src[8][32];
    int lane = threadIdx.x & 31, w = threadIdx.x >> 5;
    int d = blockIdx.x * 8 + w;
    if (d >= NN) return;
    int beg = g_rowptr[d], end = g_rowptr[d + 1];
    float2 er2 = *(const float2*)(g_er + 2 * d);
    const uint4* feat4 = (const uint4*)g_feat_h;   // 16B = 8 halves per lane
    int hl  = lane & 15;         // half-lane: covers cols 8*hl .. 8*hl+7
    int sub = lane >> 4;         // 0 -> even edges, 1 -> odd edges

    float acc[8];
    #pragma unroll
    for (int i = 0; i < 8; i++) acc[i] = 0.f;
    float z0 = 0.f, z1 = 0.f;

    for (int c = beg; c < end; c += 32) {
        int idx = c + lane;
        bool valid = idx < end;
        int s = valid ? g_srcs[idx] : 0;
        float2 el2 = *(const float2*)(g_el + 2 * s);
        float e0 = el2.x + er2.x; e0 = e0 > 0.f ? e0 : 0.2f * e0;
        float e1 = el2.y + er2.y; e1 = e1 > 0.f ? e1 : 0.2f * e1;
        float x0 = valid ? __expf(e0) : 0.f;
        float x1 = valid ? __expf(e1) : 0.f;
        z0 += x0; z1 += x1;
        s_ex[w][lane]  = make_float2(x0, x1);     // entries >= m carry ex = 0
        s_src[w][lane] = s;
        __syncwarp();
        int m = min(32, end - c);
        #pragma unroll 4
        for (int j = 0; j < m; j += 2) {
            int jj = j + sub;                     // <= 31; ex=0 pads odd tails
            int sj = s_src[w][jj];
            float2 exj = s_ex[w][jj];
            float wgt = (hl < 8) ? exj.x : exj.y; // cols<64 head0, else head1
            uint4 u = feat4[(size_t)sj * 16 + hl];
            float2 fa = __half22float2(*(const __half2*)&u.x);
            float2 fb = __half22float2(*(const __half2*)&u.y);
            float2 fc = __half22float2(*(const __half2*)&u.z);
            float2 fd = __half22float2(*(const __half2*)&u.w);
            acc[0] = fmaf(wgt, fa.x, acc[0]);
            acc[1] = fmaf(wgt, fa.y, acc[1]);
            acc[2] = fmaf(wgt, fb.x, acc[2]);
            acc[3] = fmaf(wgt, fb.y, acc[3]);
            acc[4] = fmaf(wgt, fc.x, acc[4]);
            acc[5] = fmaf(wgt, fc.y, acc[5]);
            acc[6] = fmaf(wgt, fd.x, acc[6]);
            acc[7] = fmaf(wgt, fd.y, acc[7]);
        }
        __syncwarp();
    }
    #pragma unroll
    for (int o = 16; o > 0; o >>= 1) {
        z0 += __shfl_xor_sync(0xffffffffu, z0, o);
        z1 += __shfl_xor_sync(0xffffffffu, z1, o);
    }
    // combine the two half-warps (even-edge + odd-edge partial sums)
    #pragma unroll
    for (int i = 0; i < 8; i++)
        acc[i] += __shfl_xor_sync(0xffffffffu, acc[i], 16);

    float z = (hl < 8) ? z0 : z1;
    float ia = (z > 0.f) ? __fdividef(1.f, z) : 0.f;
    if (sub == 0) {
        float4 ba = ((const float4*)bias)[2 * hl];
        float4 bb = ((const float4*)bias)[2 * hl + 1];
        __half2 h0 = __floats2half2_rn(fmaf(acc[0], ia, ba.x), fmaf(acc[1], ia, ba.y));
        __half2 h1 = __floats2half2_rn(fmaf(acc[2], ia, ba.z), fmaf(acc[3], ia, ba.w));
        __half2 h2 = __floats2half2_rn(fmaf(acc[4], ia, bb.x), fmaf(acc[5], ia, bb.y));
        __half2 h3 = __floats2half2_rn(fmaf(acc[6], ia, bb.z), fmaf(acc[7], ia, bb.w));
        uint4 outw;
        outw.x = *(unsigned*)&h0;
        outw.y = *(unsigned*)&h1;
        outw.z = *(unsigned*)&h2;
        outw.w = *(unsigned*)&h3;
        ((uint4*)g_agg_h)[(size_t)d * 16 + hl] = outw;
    }
}

// ======================= host =======================
template<typename... Args>
static inline void pdl_launch(dim3 gd, dim3 bd, void (*kfn)(Args...), Args... args) {
    cudaLaunchConfig_t cfg = {};
    cfg.gridDim = gd;
    cfg.blockDim = bd;
    cudaLaunchAttribute at[1];
    at[0].id = cudaLaunchAttributeProgrammaticStreamSerialization;
    at[0].val.programmaticStreamSerializationAllowed = 1;
    cfg.attrs = at;
    cfg.numAttrs = 1;
    cudaLaunchKernelEx(&cfg, kfn, args...);
}

extern "C" void kernel_launch(void* const* d_in, const int* in_sizes, int n_in,
                              void* d_out, int out_size) {
    const float* h     = (const float*)d_in[0];
    const int*   src   = (const int*)d_in[1];
    const int*   dst   = (const int*)d_in[2];
    const float* W1    = (const float*)d_in[3];
    const float* al1   = (const float*)d_in[4];
    const float* ar1   = (const float*)d_in[5];
    const float* b1    = (const float*)d_in[6];
    const float* lin1W = (const float*)d_in[7];
    const float* lin1b = (const float*)d_in[8];
    const float* W2    = (const float*)d_in[9];
    const float* al2   = (const float*)d_in[10];
    const float* ar2   = (const float*)d_in[11];
    const float* b2    = (const float*)d_in[12];
    const float* lin2W = (const float*)d_in[13];
    const float* lin2b = (const float*)d_in[14];
    float* out = (float*)d_out;

    void *aggp, *xp;
    cudaGetSymbolAddress(&aggp, g_agg_h);
    cudaGetSymbolAddress(&xp,   g_x_h);

    const int ROWT  = (NN + 127) / 128;           // 391
    const int EB5   = (EE + 511) / 512;           // 1563
    const int EB5H  = (EE / 2 + 511) / 512;       // 782 (2 edges/thread)
    const int NB2   = (NN / 2 + 255) / 256;       // 98 (2 nodes/thread)
    const int WARPB = (NN * 32 + 255) / 256;      // 6250 (one warp per node)

    const float* nfc = nullptr;
    void*        nv  = nullptr;

    // ---- layer-1 feat GEMM first (TRIG=true: fires early so k_hist overlaps) ----
    pdl_launch(dim3(ROWT, 2), dim3(256), gemm_mma<128, 128, true, true, false, false>,
               (const void*)h, W1, nfc, nv, (int)NN, 0, al1, ar1);

    // ---- CSR build (hist overlaps gemm1; rest is a dependent chain) ----
    pdl_launch(dim3(EB5), dim3(512), k_hist, dst);
    pdl_launch(dim3(98), dim3(512), k_scan1);
    pdl_launch(dim3(NB2), dim3(256), k_scan23);
    pdl_launch(dim3(EB5H), dim3(512), k_scatter, src, dst);

    // ---- layer 1 aggregation + lin ----
    pdl_launch(dim3(WARPB), dim3(256), gat_agg, b1);
    pdl_launch(dim3(ROWT, 1), dim3(256), gemm_mma<128, 64, false, false, true, true>,
               (const void*)aggp, lin1W, lin1b, xp, (int)NN, 1, nfc, nfc);

    // ---- layer 2 ----
    pdl_launch(dim3(ROWT, 2), dim3(256), gemm_mma<64, 128, true, false, true, false>,
               (const void*)xp, W2, nfc, nv, (int)NN, 0, al2, ar2);
    pdl_launch(dim3(WARPB), dim3(256), gat_agg, b2);
    pdl_launch(dim3(ROWT, 1), dim3(256), gemm_mma<128, 64, false, false, true, false>,
               (const void*)aggp, lin2W, lin2b, (void*)out, (int)NN, 0, nfc, nfc);
}